// round 2
// baseline (speedup 1.0000x reference)
#include <cuda_runtime.h>

// Problem constants
#define B_  8
#define S_  512
#define D_  1024
#define V_  32000
#define ND_ 8

// Scratch for hidden = hs @ W_base + b_base : [B*S, D] fp32 = 16 MB
__device__ __align__(16) float g_hidden[B_ * S_ * D_];

// ---------------------------------------------------------------------------
// Classic 128x128x8 register-tiled SGEMM body.
// A: [*, K] row-major (stride K), Bm: [K, N] row-major, bias: [N], C: [*, N].
// 256 threads, each computes an 8x8 microtile.
// ---------------------------------------------------------------------------
__device__ __forceinline__ void sgemm_body(
    const float* __restrict__ A,
    const float* __restrict__ Bm,
    const float* __restrict__ bias,
    float* __restrict__ C,
    int K, int N, int m0, int n0)
{
    __shared__ float As[8][128];
    __shared__ float Bs[8][128];

    const int t  = threadIdx.x;     // 0..255
    const int tx = t & 15;          // N-dir thread coord (0..15)
    const int ty = t >> 4;          // M-dir thread coord (0..15)

    float acc[8][8];
    #pragma unroll
    for (int i = 0; i < 8; i++)
        #pragma unroll
        for (int j = 0; j < 8; j++) acc[i][j] = 0.0f;

    // A-tile load mapping: 128 rows x 8 k = 256 float4
    const int aRow = t >> 1;            // 0..127
    const int aK4  = (t & 1) * 4;       // 0 or 4
    // B-tile load mapping: 8 rows x 128 cols = 256 float4
    const int bK   = t >> 5;            // 0..7
    const int bN4  = (t & 31) * 4;      // 0..124

    const float* Aptr = A + (size_t)(m0 + aRow) * K + aK4;
    const float* Bptr = Bm + (size_t)bK * N + n0 + bN4;

    for (int k0 = 0; k0 < K; k0 += 8) {
        float4 av = *reinterpret_cast<const float4*>(Aptr);
        float4 bv = *reinterpret_cast<const float4*>(Bptr);
        __syncthreads();   // previous iteration's smem reads done
        As[aK4 + 0][aRow] = av.x;
        As[aK4 + 1][aRow] = av.y;
        As[aK4 + 2][aRow] = av.z;
        As[aK4 + 3][aRow] = av.w;
        *reinterpret_cast<float4*>(&Bs[bK][bN4]) = bv;
        __syncthreads();
        Aptr += 8;
        Bptr += (size_t)8 * N;

        #pragma unroll
        for (int kk = 0; kk < 8; kk++) {
            float a[8], b[8];
            #pragma unroll
            for (int i = 0; i < 8; i++) a[i] = As[kk][ty * 8 + i];
            #pragma unroll
            for (int j = 0; j < 8; j++) b[j] = Bs[kk][tx * 8 + j];
            #pragma unroll
            for (int i = 0; i < 8; i++)
                #pragma unroll
                for (int j = 0; j < 8; j++)
                    acc[i][j] = fmaf(a[i], b[j], acc[i][j]);
        }
    }

    // Epilogue: add bias, vectorized stores
    #pragma unroll
    for (int i = 0; i < 8; i++) {
        const int row = m0 + ty * 8 + i;
        float* crow = C + (size_t)row * N + n0 + tx * 8;
        const float* brow = bias + n0 + tx * 8;
        #pragma unroll
        for (int j = 0; j < 8; j += 4) {
            float4 v;
            v.x = acc[i][j + 0] + brow[j + 0];
            v.y = acc[i][j + 1] + brow[j + 1];
            v.z = acc[i][j + 2] + brow[j + 2];
            v.w = acc[i][j + 3] + brow[j + 3];
            *reinterpret_cast<float4*>(crow + j) = v;
        }
    }
}

// ---------------------------------------------------------------------------
// Kernel A: hidden = hidden_states @ W_base + b_base
// grid: (N/128 = 8, M/128 = 32), block 256
// ---------------------------------------------------------------------------
__global__ __launch_bounds__(256) void base_proj_kernel(
    const float* __restrict__ hs,      // [B*S, D]
    const float* __restrict__ Wb,      // [D, D]
    const float* __restrict__ bb)      // [D]
{
    const int n0 = blockIdx.x * 128;
    const int m0 = blockIdx.y * 128;
    sgemm_body(hs, Wb, bb, g_hidden, D_, D_, m0, n0);
}

// ---------------------------------------------------------------------------
// Kernel B: out[b] = hidden[b] @ W_heads[idx[b]] + b_heads[idx[b]]
// grid: (V/128 = 250, S/128 = 4, B = 8), block 256
// ---------------------------------------------------------------------------
__global__ __launch_bounds__(256) void heads_kernel(
    const int*   __restrict__ domain_ids,  // [B]
    const float* __restrict__ W_heads,     // [ND+1, D, V]
    const float* __restrict__ b_heads,     // [ND+1, V]
    float* __restrict__ out)               // [B, S, V]
{
    const int b = blockIdx.z;
    int id = domain_ids[b];
    const int idx = (id >= 0 && id < ND_) ? id : ND_;

    const float* A    = g_hidden + (size_t)b * S_ * D_;
    const float* Bm   = W_heads + (size_t)idx * D_ * V_;
    const float* bias = b_heads + (size_t)idx * V_;
    float* C          = out + (size_t)b * S_ * V_;

    const int n0 = blockIdx.x * 128;
    const int m0 = blockIdx.y * 128;
    sgemm_body(A, Bm, bias, C, D_, V_, m0, n0);
}

// ---------------------------------------------------------------------------
// Launch
// inputs (metadata order): hidden_states f32, domain_ids i32, W_base f32,
//                          b_base f32, W_heads f32, b_heads f32
// ---------------------------------------------------------------------------
extern "C" void kernel_launch(void* const* d_in, const int* in_sizes, int n_in,
                              void* d_out, int out_size)
{
    const float* hs      = (const float*)d_in[0];
    const int*   dom     = (const int*)  d_in[1];
    const float* W_base  = (const float*)d_in[2];
    const float* b_base  = (const float*)d_in[3];
    const float* W_heads = (const float*)d_in[4];
    const float* b_heads = (const float*)d_in[5];
    float* out = (float*)d_out;

    dim3 gridA(D_ / 128, (B_ * S_) / 128);    // (8, 32)
    base_proj_kernel<<<gridA, 256>>>(hs, W_base, b_base);

    dim3 gridB(V_ / 128, S_ / 128, B_);       // (250, 4, 8)
    heads_kernel<<<gridB, 256>>>(dom, W_heads, b_heads, out);
}